// round 13
// baseline (speedup 1.0000x reference)
#include <cuda_runtime.h>
#include <cuda_bf16.h>
#include <math.h>
#include <stdint.h>

#define HDIM 1024
#define IC   4096
#define PH   4096
#define TH   2048
#define NTILES 30
#define MAXM 14592

#if defined(__CUDA_ARCH__)
#  if defined(__CUDA_ARCH_FEAT_SM103_ALL) || defined(__CUDA_ARCH_FEAT_SM100_ALL) || \
      defined(__CUDA_ARCH_FEAT_SM101_ALL) || \
      (defined(__CUDA_ARCH_SPECIFIC__) && (__CUDA_ARCH_SPECIFIC__ >= 1000))
#    define HAS_TCGEN05 1
#  else
#    define HAS_TCGEN05 0
#  endif
#else
#  define HAS_TCGEN05 0
#endif

// ------------------------- device scratch (no allocs) -----------------------
__device__ int   g_meta[NTILES * 4];
__device__ __nv_bfloat16 g_Xhi[(size_t)MAXM * IC];
__device__ __nv_bfloat16 g_Xlo[(size_t)MAXM * IC];
__device__ __nv_bfloat16 g_Hhi[(size_t)MAXM * PH];
__device__ __nv_bfloat16 g_Hlo[(size_t)MAXM * PH];
__device__ __nv_bfloat16 g_W1hi[(size_t)PH * IC];   // W1^T hi [N,K]
__device__ __nv_bfloat16 g_W1lo[(size_t)PH * IC];
__device__ __nv_bfloat16 g_W2hi[(size_t)TH * PH];   // W2^T hi [N,K]
__device__ __nv_bfloat16 g_W2lo[(size_t)TH * PH];

// ------------------------------ helpers ------------------------------------
__device__ __forceinline__ float gelu_exact(float x) {
    return 0.5f * x * (1.0f + erff(x * 0.70710678118654752440f));
}

#if HAS_TCGEN05
__device__ __forceinline__ uint32_t smem_u32(const void* p) {
    uint32_t a;
    asm("{ .reg .u64 t; cvta.to.shared.u64 t, %1; cvt.u32.u64 %0, t; }" : "=r"(a) : "l"(p));
    return a;
}

__device__ __forceinline__ uint32_t elect_one_pred() {
    uint32_t pred;
    asm volatile(
        "{\n\t.reg .pred p;\n\t"
        "elect.sync _|p, 0xFFFFFFFF;\n\t"
        "selp.b32 %0, 1, 0, p;\n\t}"
        : "=r"(pred));
    return pred;
}

__device__ __forceinline__ void mbar_init(uint32_t m, uint32_t cnt) {
    asm volatile("mbarrier.init.shared.b64 [%0], %1;" :: "r"(m), "r"(cnt) : "memory");
}
__device__ __forceinline__ void mbar_inval(uint32_t m) {
    asm volatile("mbarrier.inval.shared.b64 [%0];" :: "r"(m) : "memory");
}
__device__ __forceinline__ void mbar_wait(uint32_t m, uint32_t phase) {
    asm volatile(
        "{\n\t.reg .pred P;\n\t"
        "LAB_WAIT_%=:\n\t"
        "mbarrier.try_wait.parity.acquire.cta.shared::cta.b64 P, [%0], %1, 0x989680;\n\t"
        "@P bra LAB_DONE_%=;\n\t"
        "bra LAB_WAIT_%=;\n\t"
        "LAB_DONE_%=:\n\t}"
        :: "r"(m), "r"(phase) : "memory");
}

__device__ __forceinline__ void cp_async16(uint32_t dst, const void* src) {
    asm volatile("cp.async.cg.shared.global [%0], [%1], 16;" :: "r"(dst), "l"(src) : "memory");
}
__device__ __forceinline__ void cp_commit() {
    asm volatile("cp.async.commit_group;" ::: "memory");
}
__device__ __forceinline__ void cp_wait0() {
    asm volatile("cp.async.wait_group 0;" ::: "memory");
}
__device__ __forceinline__ void fence_proxy_async_cta() {
    asm volatile("fence.proxy.async.shared::cta;" ::: "memory");
}

__device__ __forceinline__ void tmem_alloc(uint32_t smem_dst, uint32_t ncols) {
    asm volatile("tcgen05.alloc.cta_group::1.sync.aligned.shared::cta.b32 [%0], %1;"
                 :: "r"(smem_dst), "r"(ncols) : "memory");
}
__device__ __forceinline__ void tmem_dealloc(uint32_t tmem, uint32_t ncols) {
    asm volatile("tcgen05.dealloc.cta_group::1.sync.aligned.b32 %0, %1;" :: "r"(tmem), "r"(ncols));
}

// SS f16 MMA, cg1, 4-reg disable-lane vector
__device__ __forceinline__ void mma_f16_ss(uint32_t d, uint64_t ad, uint64_t bd,
                                           uint32_t idesc, uint32_t en) {
    asm volatile(
        "{\n\t.reg .pred p;\n\t"
        "setp.ne.u32 p, %4, 0;\n\t"
        "tcgen05.mma.cta_group::1.kind::f16 [%0], %1, %2, %3, {%5, %5, %5, %5}, p;\n\t}"
        :: "r"(d), "l"(ad), "l"(bd), "r"(idesc), "r"(en), "r"(0u) : "memory");
}

__device__ __forceinline__ void mma_commit(uint32_t mbar) {
    asm volatile(
        "tcgen05.commit.cta_group::1.mbarrier::arrive::one.shared::cluster.b64 [%0];"
        :: "r"(mbar) : "memory");
}

#define TCGEN05_LD_X32(r, addr) \
    asm volatile( \
        "tcgen05.ld.sync.aligned.32x32b.x32.b32 " \
        "{%0, %1, %2, %3, %4, %5, %6, %7, " \
        " %8, %9, %10, %11, %12, %13, %14, %15, " \
        " %16, %17, %18, %19, %20, %21, %22, %23, " \
        " %24, %25, %26, %27, %28, %29, %30, %31}, [%32];" \
        : "=r"((r)[0]),  "=r"((r)[1]),  "=r"((r)[2]),  "=r"((r)[3]), \
          "=r"((r)[4]),  "=r"((r)[5]),  "=r"((r)[6]),  "=r"((r)[7]), \
          "=r"((r)[8]),  "=r"((r)[9]),  "=r"((r)[10]), "=r"((r)[11]), \
          "=r"((r)[12]), "=r"((r)[13]), "=r"((r)[14]), "=r"((r)[15]), \
          "=r"((r)[16]), "=r"((r)[17]), "=r"((r)[18]), "=r"((r)[19]), \
          "=r"((r)[20]), "=r"((r)[21]), "=r"((r)[22]), "=r"((r)[23]), \
          "=r"((r)[24]), "=r"((r)[25]), "=r"((r)[26]), "=r"((r)[27]), \
          "=r"((r)[28]), "=r"((r)[29]), "=r"((r)[30]), "=r"((r)[31]) \
        : "r"(addr))

__device__ __forceinline__ void tmem_wait_ld() {
    asm volatile("tcgen05.wait::ld.sync.aligned;" ::: "memory");
}
__device__ __forceinline__ void tc_fence_after() {
    asm volatile("tcgen05.fence::after_thread_sync;" ::: "memory");
}
__device__ __forceinline__ void tc_fence_before() {
    asm volatile("tcgen05.fence::before_thread_sync;" ::: "memory");
}

// SW64 descriptor: layout=4, version=1, SBO=32 (512B = 8 rows x 64B), LBO=1
static __device__ __forceinline__ uint64_t make_desc64(uint32_t addr) {
    const uint64_t base = (4ull << 61) | (1ull << 46) | (32ull << 32) | (1ull << 16);
    return base | ((uint64_t)(addr >> 4) & 0x3FFF);
}
#endif  // HAS_TCGEN05

#define SWZ64(x) ((x) ^ (((x) >> 3) & 0x30))

// ----------------------------------------------------------------------------
__global__ void meta_kernel(const int* __restrict__ ss) {
    if (threadIdx.x == 0 && blockIdx.x == 0) {
        int is64 = (ss[1] == 0) ? 1 : 0;
        int in_off = 0, out_off = 0;
        for (int t = 0; t < NTILES; t++) {
            int h, w;
            if (is64) { h = ss[4 * t]; w = ss[4 * t + 2]; }
            else      { h = ss[2 * t]; w = ss[2 * t + 1]; }
            g_meta[4 * t + 0] = h;
            g_meta[4 * t + 1] = w;
            g_meta[4 * t + 2] = in_off;
            g_meta[4 * t + 3] = out_off;
            in_off  += h * w;
            out_off += (h >> 1) * (w >> 1);
        }
    }
}

// ----------------------------------------------------------------------------
// gather + LayerNorm -> bf16 hi/lo planes
// ----------------------------------------------------------------------------
__global__ void __launch_bounds__(256) gather_ln_kernel(
    const float* __restrict__ vf,
    const float* __restrict__ gamma,
    const float* __restrict__ beta)
{
    const int r   = blockIdx.x;
    const int tid = threadIdx.x;

    __shared__ int   srows[4];
    __shared__ float sred[2][8];
    __shared__ float sstat[2];

    if (tid == 0) {
        int t = 0;
        #pragma unroll 1
        for (int i = 0; i < NTILES; i++) {
            int h  = g_meta[4 * i + 0];
            int w  = g_meta[4 * i + 1];
            int oo = g_meta[4 * i + 3];
            int cnt = (h >> 1) * (w >> 1);
            if (r >= oo && r < oo + cnt) { t = i; break; }
        }
        int w  = g_meta[4 * t + 1];
        int io = g_meta[4 * t + 2];
        int oo = g_meta[4 * t + 3];
        int local = r - oo;
        int wb = w >> 1;
        int bh = local / wb;
        int bw = local - bh * wb;
        srows[0] = io + (2 * bh)     * w + 2 * bw;
        srows[1] = io + (2 * bh)     * w + 2 * bw + 1;
        srows[2] = io + (2 * bh + 1) * w + 2 * bw;
        srows[3] = io + (2 * bh + 1) * w + 2 * bw + 1;
    }
    __syncthreads();

    float vals[16];
    float s = 0.f, s2 = 0.f;
    #pragma unroll
    for (int i = 0; i < 16; i++) {
        int f      = tid + i * 256;
        int c      = f >> 10;
        int within = f & 1023;
        float v = vf[(size_t)srows[c] * HDIM + within];
        vals[i] = v;
        s  += v;
        s2 += v * v;
    }

    #pragma unroll
    for (int o = 16; o > 0; o >>= 1) {
        s  += __shfl_down_sync(0xFFFFFFFFu, s, o);
        s2 += __shfl_down_sync(0xFFFFFFFFu, s2, o);
    }
    if ((tid & 31) == 0) { sred[0][tid >> 5] = s; sred[1][tid >> 5] = s2; }
    __syncthreads();
    if (tid < 32) {
        float a = (tid < 8) ? sred[0][tid] : 0.f;
        float b = (tid < 8) ? sred[1][tid] : 0.f;
        #pragma unroll
        for (int o = 4; o > 0; o >>= 1) {
            a += __shfl_down_sync(0xFFFFFFFFu, a, o);
            b += __shfl_down_sync(0xFFFFFFFFu, b, o);
        }
        if (tid == 0) {
            float mu  = a * (1.0f / IC);
            float var = b * (1.0f / IC) - mu * mu;
            sstat[0] = mu;
            sstat[1] = rsqrtf(var + 1e-5f);
        }
    }
    __syncthreads();

    float mu   = sstat[0];
    float rstd = sstat[1];
    size_t rowb = (size_t)r * IC;
    #pragma unroll
    for (int i = 0; i < 16; i++) {
        int f = tid + i * 256;
        float y = (vals[i] - mu) * rstd * gamma[f] + beta[f];
        __nv_bfloat16 h = __float2bfloat16(y);
        g_Xhi[rowb + f] = h;
        g_Xlo[rowb + f] = __float2bfloat16(y - __bfloat162float(h));
    }
}

// ----------------------------------------------------------------------------
// weight transpose + bf16 hi/lo split:  W[K,N] fp32 -> T_hi/T_lo [N,K] bf16
// ----------------------------------------------------------------------------
__global__ void __launch_bounds__(256) wconv_kernel(
    const float* __restrict__ W,
    __nv_bfloat16* __restrict__ Thi,
    __nv_bfloat16* __restrict__ Tlo,
    int K, int N)
{
    __shared__ float tile[32][33];
    int tx = threadIdx.x, ty = threadIdx.y;         // 32 x 8
    int n0 = blockIdx.x * 32, k0 = blockIdx.y * 32;
    #pragma unroll
    for (int j = 0; j < 4; j++)
        tile[ty + 8 * j][tx] = W[(size_t)(k0 + ty + 8 * j) * N + n0 + tx];
    __syncthreads();
    #pragma unroll
    for (int j = 0; j < 4; j++) {
        float v = tile[tx][ty + 8 * j];
        __nv_bfloat16 h = __float2bfloat16(v);
        size_t o = (size_t)(n0 + ty + 8 * j) * K + k0 + tx;
        Thi[o] = h;
        Tlo[o] = __float2bfloat16(v - __bfloat162float(h));
    }
}

// ----------------------------------------------------------------------------
// tcgen05 SS-mode split-bf16 GEMM, 256x256 CTA tile, KCHUNK=32, SW64 layout:
//   C[M,N] = epi( A[M,K] @ B[N,K]^T + bias )
//   Stage (64KB): Ah0|Al0|Ah1|Al1 (8KB each, 128 rows x 64B) |
//                 Bh|Bl (16KB each, 256 rows x 64B).  2 stages.
//   TMEM: D0 @0..255, D1 @256..511 (alloc 512).
//   Per chunk: 2 k-steps x 3 split terms x 2 D tiles = 12 MMAs (N=256).
// ----------------------------------------------------------------------------
#define KCHUNK  32
#define STAGEB  65536
#define DSMEMB  (2 * STAGEB + 1024)
#define IDESC_V ((1u<<4)|(1u<<7)|(1u<<10)|(32u<<17)|(8u<<24))   // N=256

__global__ void __launch_bounds__(256) __cluster_dims__(1, 1, 1) gemm_kernel(
    const __nv_bfloat16* __restrict__ Ahi,
    const __nv_bfloat16* __restrict__ Alo,
    const __nv_bfloat16* __restrict__ Bhi,
    const __nv_bfloat16* __restrict__ Blo,
    const float* __restrict__ bias,
    float* __restrict__ outF,
    __nv_bfloat16* __restrict__ outHi,
    __nv_bfloat16* __restrict__ outLo,
    int M, int K, int Nfull, int mode)
{
#if HAS_TCGEN05
    extern __shared__ char dsm_raw[];
    __shared__ __align__(8) uint64_t s_bar[1];
    __shared__ __align__(4) uint32_t s_tmem[1];

    const int tid = threadIdx.x;
    const int wid = tid >> 5;
    const int bm  = blockIdx.y * 256;
    const int bn  = blockIdx.x * 256;
    const int nk  = K / KCHUNK;

    uint32_t stage = (smem_u32(dsm_raw) + 1023u) & ~1023u;
    uint32_t bMma  = smem_u32(&s_bar[0]);

    if (wid == 0) tmem_alloc(smem_u32(s_tmem), 512);
    if (tid == 0) mbar_init(bMma, 1);
    __syncthreads();
    uint32_t tmem;
    asm volatile("ld.shared.b32 %0, [%1];" : "=r"(tmem) : "r"(smem_u32(s_tmem)));

    const size_t kb = (size_t)K * 2;   // row bytes (bf16)
    // plane order: Ah0 Al0 Ah1 Al1 (8KB each) Bh Bl (16KB each)
    const char* plnA[4] = { (const char*)Ahi, (const char*)Alo,
                            (const char*)Ahi, (const char*)Alo };
    const char* plnB[2] = { (const char*)Bhi, (const char*)Blo };
    const uint32_t pOffA[4] = { 0u, 8192u, 16384u, 24576u };
    const uint32_t pOffB[2] = { 32768u, 49152u };

    // loads one K-chunk into stage buffer (c & 1): 4096 x 16B via cp.async
    auto load_stage = [&](int c) {
        uint32_t sb = stage + (uint32_t)(c & 1) * STAGEB;
        size_t koff = (size_t)c * (KCHUNK * 2);   // 64 bytes per chunk step
        #pragma unroll
        for (int i = 0; i < 16; ++i) {
            int q = tid + 256 * i;
            const char* src;
            uint32_t dst;
            if (q < 2048) {                    // A region: 4 planes x 512 chunks
                int plane = q >> 9;
                int idx   = q & 511;
                int row   = idx >> 2;          // 0..127
                int ch    = idx & 3;           // 4 x 16B per 64B row
                int grow  = bm + (plane >> 1) * 128 + row;
                src = plnA[plane] + (size_t)grow * kb + koff + ch * 16;
                dst = sb + pOffA[plane] + SWZ64(row * 64 + ch * 16);
            } else {                           // B region: 2 planes x 1024 chunks
                int r2    = q - 2048;
                int plane = r2 >> 10;
                int idx   = r2 & 1023;
                int row   = idx >> 2;          // 0..255
                int ch    = idx & 3;
                int grow  = bn + row;
                src = plnB[plane] + (size_t)grow * kb + koff + ch * 16;
                dst = sb + pOffB[plane] + SWZ64(row * 64 + ch * 16);
            }
            cp_async16(dst, src);
        }
        cp_commit();
    };

    load_stage(0);

    for (int c = 0; c < nk; ++c) {
        cp_wait0();                 // chunk c resident
        fence_proxy_async_cta();
        tc_fence_before();
        __syncthreads();

        // prefetch next chunk; its buffer was read by MMA (c-1) -> wait it
        if (c + 1 < nk) {
            if (c >= 1) mbar_wait(bMma, (uint32_t)((c - 1) & 1));
            load_stage(c + 1);
        }

        // MMA: warp 0 elect issues 12 MMAs for this chunk (2 D tiles, N=256)
        if (wid == 0) {
            tc_fence_after();
            if (elect_one_pred()) {
                uint32_t sb = stage + (uint32_t)(c & 1) * STAGEB;
                uint64_t dA[2][2] = {
                    { make_desc64(sb + pOffA[0]), make_desc64(sb + pOffA[1]) },
                    { make_desc64(sb + pOffA[2]), make_desc64(sb + pOffA[3]) } };
                uint64_t dBh = make_desc64(sb + pOffB[0]);
                uint64_t dBl = make_desc64(sb + pOffB[1]);
                #pragma unroll
                for (int ks = 0; ks < 2; ++ks) {
                    uint64_t o = (uint64_t)(ks * 2);   // 32B = 2 x 16B units
                    uint32_t acc = (c > 0 || ks > 0) ? 1u : 0u;
                    #pragma unroll
                    for (int tI = 0; tI < 2; ++tI) {
                        uint32_t d = tmem + tI * 256;
                        mma_f16_ss(d, dA[tI][0] + o, dBh + o, IDESC_V, acc);
                        mma_f16_ss(d, dA[tI][1] + o, dBh + o, IDESC_V, 1);
                        mma_f16_ss(d, dA[tI][0] + o, dBl + o, IDESC_V, 1);
                    }
                }
                mma_commit(bMma);
            }
        }
    }

    mbar_wait(bMma, (uint32_t)((nk - 1) & 1));
    __syncthreads();
    tc_fence_after();

    // --------- epilogue: 8 warps = 4 row-subparts x 2 M-subtiles -----------
    const int lane = tid & 31;
    const int sub  = wid & 3;          // TMEM lane subpartition
    const int tI   = wid >> 2;         // M subtile / D tile
    const int row  = bm + tI * 128 + sub * 32 + lane;
    const uint32_t woff = ((uint32_t)sub) << 21;

    #pragma unroll 1
    for (int b = 0; b < 8; ++b) {
        uint32_t r[32];
        TCGEN05_LD_X32(r, tmem + tI * 256 + b * 32 + woff);
        tmem_wait_ld();
        int col0 = bn + b * 32;
        if (mode) {
            __align__(16) __nv_bfloat16 hv[32], lv[32];
            #pragma unroll
            for (int j = 0; j < 32; ++j) {
                float v = __uint_as_float(r[j]) + bias[col0 + j];
                v = gelu_exact(v);
                __nv_bfloat16 h = __float2bfloat16(v);
                hv[j] = h;
                lv[j] = __float2bfloat16(v - __bfloat162float(h));
            }
            uint4* dh = (uint4*)(outHi + (size_t)row * Nfull + col0);
            uint4* dl = (uint4*)(outLo + (size_t)row * Nfull + col0);
            #pragma unroll
            for (int u = 0; u < 4; ++u) { dh[u] = ((uint4*)hv)[u]; dl[u] = ((uint4*)lv)[u]; }
        } else {
            float* dp = outF + (size_t)row * Nfull + col0;
            #pragma unroll
            for (int j = 0; j < 32; j += 4) {
                float4 v;
                v.x = __uint_as_float(r[j + 0]) + bias[col0 + j + 0];
                v.y = __uint_as_float(r[j + 1]) + bias[col0 + j + 1];
                v.z = __uint_as_float(r[j + 2]) + bias[col0 + j + 2];
                v.w = __uint_as_float(r[j + 3]) + bias[col0 + j + 3];
                *(float4*)(dp + j) = v;
            }
        }
    }

    tc_fence_before();
    __syncthreads();
    if (tid == 0) mbar_inval(bMma);
    __syncthreads();
    if (wid == 0) tmem_dealloc(tmem, 512);

#else  // ------------------- FFMA fallback (plain sm_103 pass) ---------------
    extern __shared__ char dsm_raw[];
    float* As = (float*)dsm_raw;                  // [16][128]
    float* Bs = (float*)(dsm_raw + 16 * 128 * 4); // [16][64]

    const int tid = threadIdx.x & 127;
    const int ty  = tid >> 4;
    const int tx  = tid & 15;
    const int bn0 = blockIdx.x * 256;
    if (threadIdx.x >= 128) return;

    for (int msub = 0; msub < 2; ++msub) {
        const int bm = blockIdx.y * 256 + msub * 128;
        for (int ns = 0; ns < 4; ++ns) {
            int bn = bn0 + ns * 64;
            float acc[16][4];
            #pragma unroll
            for (int i = 0; i < 16; i++)
                #pragma unroll
                for (int j = 0; j < 4; j++) acc[i][j] = 0.f;

            for (int k0 = 0; k0 < K; k0 += 16) {
                #pragma unroll
                for (int i = 0; i < 16; i++) {
                    int idx = tid + 128 * i;
                    int row = idx >> 4, kk = idx & 15;
                    size_t go = (size_t)(bm + row) * K + k0 + kk;
                    As[kk * 128 + row] = __bfloat162float(Ahi[go]) + __bfloat162float(Alo[go]);
                }
                #pragma unroll
                for (int i = 0; i < 8; i++) {
                    int idx = tid + 128 * i;
                    int n = idx >> 4, kk = idx & 15;
                    size_t go = (size_t)(bn + n) * K + k0 + kk;
                    Bs[kk * 64 + n] = __bfloat162float(Bhi[go]) + __bfloat162float(Blo[go]);
                }
                __syncthreads();
                #pragma unroll
                for (int kk = 0; kk < 16; kk++) {
                    float bvals[4];
                    #pragma unroll
                    for (int j = 0; j < 4; j++) bvals[j] = Bs[kk * 64 + tx * 4 + j];
                    #pragma unroll
                    for (int i = 0; i < 16; i++) {
                        float av = As[kk * 128 + ty * 16 + i];
                        #pragma unroll
                        for (int j = 0; j < 4; j++) acc[i][j] += av * bvals[j];
                    }
                }
                __syncthreads();
            }

            #pragma unroll
            for (int i = 0; i < 16; i++) {
                int row = bm + ty * 16 + i;
                #pragma unroll
                for (int j = 0; j < 4; j++) {
                    int col = bn + tx * 4 + j;
                    float v = acc[i][j] + bias[col];
                    if (mode) {
                        v = gelu_exact(v);
                        __nv_bfloat16 h = __float2bfloat16(v);
                        outHi[(size_t)row * Nfull + col] = h;
                        outLo[(size_t)row * Nfull + col] = __float2bfloat16(v - __bfloat162float(h));
                    } else {
                        outF[(size_t)row * Nfull + col] = v;
                    }
                }
            }
            __syncthreads();
        }
    }
#endif
}

// ----------------------------------------------------------------------------
extern "C" void kernel_launch(void* const* d_in, const int* in_sizes, int n_in,
                              void* d_out, int out_size)
{
    const float* vf    = (const float*)d_in[0];
    const int*   ss    = (const int*)  d_in[1];
    const float* gamma = (const float*)d_in[2];
    const float* beta  = (const float*)d_in[3];
    const float* w1    = (const float*)d_in[4];
    const float* b1    = (const float*)d_in[5];
    const float* w2    = (const float*)d_in[6];
    const float* b2    = (const float*)d_in[7];
    float* out = (float*)d_out;

    int total_tokens = in_sizes[0] / HDIM;
    int M = total_tokens / 4;
    if (M > MAXM) M = MAXM;

    __nv_bfloat16 *xhi, *xlo, *hhi, *hlo, *w1hi, *w1lo, *w2hi, *w2lo;
    cudaGetSymbolAddress((void**)&xhi,  g_Xhi);
    cudaGetSymbolAddress((void**)&xlo,  g_Xlo);
    cudaGetSymbolAddress((void**)&hhi,  g_Hhi);
    cudaGetSymbolAddress((void**)&hlo,  g_Hlo);
    cudaGetSymbolAddress((void**)&w1hi, g_W1hi);
    cudaGetSymbolAddress((void**)&w1lo, g_W1lo);
    cudaGetSymbolAddress((void**)&w2hi, g_W2hi);
    cudaGetSymbolAddress((void**)&w2lo, g_W2lo);

    cudaFuncSetAttribute(gemm_kernel, cudaFuncAttributeMaxDynamicSharedMemorySize, DSMEMB);

    meta_kernel<<<1, 32>>>(ss);
    gather_ln_kernel<<<M, 256>>>(vf, gamma, beta);

    dim3 wb(32, 8);
    wconv_kernel<<<dim3(PH / 32, IC / 32), wb>>>(w1, w1hi, w1lo, IC, PH);
    wconv_kernel<<<dim3(TH / 32, PH / 32), wb>>>(w2, w2hi, w2lo, PH, TH);

    int Mt = (M + 255) / 256;
    gemm_kernel<<<dim3(PH / 256, Mt), 256, DSMEMB>>>(
        xhi, xlo, w1hi, w1lo, b1, nullptr, hhi, hlo, M, IC, PH, 1);
    gemm_kernel<<<dim3(TH / 256, Mt), 256, DSMEMB>>>(
        hhi, hlo, w2hi, w2lo, b2, out, nullptr, nullptr, M, PH, TH, 0);
}

// round 14
// speedup vs baseline: 2.1756x; 2.1756x over previous
#include <cuda_runtime.h>
#include <cuda_fp16.h>
#include <math.h>
#include <stdint.h>

#define HDIM 1024
#define IC   4096
#define PH   4096
#define TH   2048
#define NTILES 30
#define MAXM 14592

#if defined(__CUDA_ARCH__)
#  if defined(__CUDA_ARCH_FEAT_SM103_ALL) || defined(__CUDA_ARCH_FEAT_SM100_ALL) || \
      defined(__CUDA_ARCH_FEAT_SM101_ALL) || \
      (defined(__CUDA_ARCH_SPECIFIC__) && (__CUDA_ARCH_SPECIFIC__ >= 1000))
#    define HAS_TCGEN05 1
#  else
#    define HAS_TCGEN05 0
#  endif
#else
#  define HAS_TCGEN05 0
#endif

// ------------------------- device scratch (no allocs) -----------------------
__device__ int    g_meta[NTILES * 4];
__device__ __half g_X [(size_t)MAXM * IC];     // post-LN fp16
__device__ __half g_H [(size_t)MAXM * PH];     // post-GELU fp16
__device__ __half g_W1[(size_t)PH * IC];       // W1^T fp16 [N,K]
__device__ __half g_W2[(size_t)TH * PH];       // W2^T fp16 [N,K]

// ------------------------------ helpers ------------------------------------
__device__ __forceinline__ float gelu_exact(float x) {
    return 0.5f * x * (1.0f + erff(x * 0.70710678118654752440f));
}

#if HAS_TCGEN05
__device__ __forceinline__ uint32_t smem_u32(const void* p) {
    uint32_t a;
    asm("{ .reg .u64 t; cvta.to.shared.u64 t, %1; cvt.u32.u64 %0, t; }" : "=r"(a) : "l"(p));
    return a;
}

__device__ __forceinline__ uint32_t elect_one_pred() {
    uint32_t pred;
    asm volatile(
        "{\n\t.reg .pred p;\n\t"
        "elect.sync _|p, 0xFFFFFFFF;\n\t"
        "selp.b32 %0, 1, 0, p;\n\t}"
        : "=r"(pred));
    return pred;
}

__device__ __forceinline__ void mbar_init(uint32_t m, uint32_t cnt) {
    asm volatile("mbarrier.init.shared.b64 [%0], %1;" :: "r"(m), "r"(cnt) : "memory");
}
__device__ __forceinline__ void mbar_inval(uint32_t m) {
    asm volatile("mbarrier.inval.shared.b64 [%0];" :: "r"(m) : "memory");
}
__device__ __forceinline__ void mbar_wait(uint32_t m, uint32_t phase) {
    asm volatile(
        "{\n\t.reg .pred P;\n\t"
        "LAB_WAIT_%=:\n\t"
        "mbarrier.try_wait.parity.acquire.cta.shared::cta.b64 P, [%0], %1, 0x989680;\n\t"
        "@P bra LAB_DONE_%=;\n\t"
        "bra LAB_WAIT_%=;\n\t"
        "LAB_DONE_%=:\n\t}"
        :: "r"(m), "r"(phase) : "memory");
}

__device__ __forceinline__ void cp_async16(uint32_t dst, const void* src) {
    asm volatile("cp.async.cg.shared.global [%0], [%1], 16;" :: "r"(dst), "l"(src) : "memory");
}
__device__ __forceinline__ void cp_commit() {
    asm volatile("cp.async.commit_group;" ::: "memory");
}
__device__ __forceinline__ void cp_wait0() {
    asm volatile("cp.async.wait_group 0;" ::: "memory");
}
__device__ __forceinline__ void fence_proxy_async_cta() {
    asm volatile("fence.proxy.async.shared::cta;" ::: "memory");
}

__device__ __forceinline__ void tmem_alloc(uint32_t smem_dst, uint32_t ncols) {
    asm volatile("tcgen05.alloc.cta_group::1.sync.aligned.shared::cta.b32 [%0], %1;"
                 :: "r"(smem_dst), "r"(ncols) : "memory");
}
__device__ __forceinline__ void tmem_dealloc(uint32_t tmem, uint32_t ncols) {
    asm volatile("tcgen05.dealloc.cta_group::1.sync.aligned.b32 %0, %1;" :: "r"(tmem), "r"(ncols));
}

// SS f16 MMA, cg1, 4-reg disable-lane vector
__device__ __forceinline__ void mma_f16_ss(uint32_t d, uint64_t ad, uint64_t bd,
                                           uint32_t idesc, uint32_t en) {
    asm volatile(
        "{\n\t.reg .pred p;\n\t"
        "setp.ne.u32 p, %4, 0;\n\t"
        "tcgen05.mma.cta_group::1.kind::f16 [%0], %1, %2, %3, {%5, %5, %5, %5}, p;\n\t}"
        :: "r"(d), "l"(ad), "l"(bd), "r"(idesc), "r"(en), "r"(0u) : "memory");
}

__device__ __forceinline__ void mma_commit(uint32_t mbar) {
    asm volatile(
        "tcgen05.commit.cta_group::1.mbarrier::arrive::one.shared::cluster.b64 [%0];"
        :: "r"(mbar) : "memory");
}

#define TCGEN05_LD_X32(r, addr) \
    asm volatile( \
        "tcgen05.ld.sync.aligned.32x32b.x32.b32 " \
        "{%0, %1, %2, %3, %4, %5, %6, %7, " \
        " %8, %9, %10, %11, %12, %13, %14, %15, " \
        " %16, %17, %18, %19, %20, %21, %22, %23, " \
        " %24, %25, %26, %27, %28, %29, %30, %31}, [%32];" \
        : "=r"((r)[0]),  "=r"((r)[1]),  "=r"((r)[2]),  "=r"((r)[3]), \
          "=r"((r)[4]),  "=r"((r)[5]),  "=r"((r)[6]),  "=r"((r)[7]), \
          "=r"((r)[8]),  "=r"((r)[9]),  "=r"((r)[10]), "=r"((r)[11]), \
          "=r"((r)[12]), "=r"((r)[13]), "=r"((r)[14]), "=r"((r)[15]), \
          "=r"((r)[16]), "=r"((r)[17]), "=r"((r)[18]), "=r"((r)[19]), \
          "=r"((r)[20]), "=r"((r)[21]), "=r"((r)[22]), "=r"((r)[23]), \
          "=r"((r)[24]), "=r"((r)[25]), "=r"((r)[26]), "=r"((r)[27]), \
          "=r"((r)[28]), "=r"((r)[29]), "=r"((r)[30]), "=r"((r)[31]) \
        : "r"(addr))

__device__ __forceinline__ void tmem_wait_ld() {
    asm volatile("tcgen05.wait::ld.sync.aligned;" ::: "memory");
}
__device__ __forceinline__ void tc_fence_after() {
    asm volatile("tcgen05.fence::after_thread_sync;" ::: "memory");
}
__device__ __forceinline__ void tc_fence_before() {
    asm volatile("tcgen05.fence::before_thread_sync;" ::: "memory");
}

// SW128 K-major descriptor (verified): layout=2, version=1, SBO=64, LBO=1
static __device__ __forceinline__ uint64_t make_desc(uint32_t addr) {
    const uint64_t base = (2ull << 61) | (1ull << 46) | (64ull << 32) | (1ull << 16);
    return base | ((uint64_t)(addr >> 4) & 0x3FFF);
}
#endif  // HAS_TCGEN05

#define SWZ(x) ((x) ^ (((x) >> 3) & 0x70))

// ----------------------------------------------------------------------------
__global__ void meta_kernel(const int* __restrict__ ss) {
    if (threadIdx.x == 0 && blockIdx.x == 0) {
        int is64 = (ss[1] == 0) ? 1 : 0;
        int in_off = 0, out_off = 0;
        for (int t = 0; t < NTILES; t++) {
            int h, w;
            if (is64) { h = ss[4 * t]; w = ss[4 * t + 2]; }
            else      { h = ss[2 * t]; w = ss[2 * t + 1]; }
            g_meta[4 * t + 0] = h;
            g_meta[4 * t + 1] = w;
            g_meta[4 * t + 2] = in_off;
            g_meta[4 * t + 3] = out_off;
            in_off  += h * w;
            out_off += (h >> 1) * (w >> 1);
        }
    }
}

// ----------------------------------------------------------------------------
// gather + LayerNorm -> fp16
// ----------------------------------------------------------------------------
__global__ void __launch_bounds__(256) gather_ln_kernel(
    const float* __restrict__ vf,
    const float* __restrict__ gamma,
    const float* __restrict__ beta)
{
    const int r   = blockIdx.x;
    const int tid = threadIdx.x;

    __shared__ int   srows[4];
    __shared__ float sred[2][8];
    __shared__ float sstat[2];

    if (tid == 0) {
        int t = 0;
        #pragma unroll 1
        for (int i = 0; i < NTILES; i++) {
            int h  = g_meta[4 * i + 0];
            int w  = g_meta[4 * i + 1];
            int oo = g_meta[4 * i + 3];
            int cnt = (h >> 1) * (w >> 1);
            if (r >= oo && r < oo + cnt) { t = i; break; }
        }
        int w  = g_meta[4 * t + 1];
        int io = g_meta[4 * t + 2];
        int oo = g_meta[4 * t + 3];
        int local = r - oo;
        int wb = w >> 1;
        int bh = local / wb;
        int bw = local - bh * wb;
        srows[0] = io + (2 * bh)     * w + 2 * bw;
        srows[1] = io + (2 * bh)     * w + 2 * bw + 1;
        srows[2] = io + (2 * bh + 1) * w + 2 * bw;
        srows[3] = io + (2 * bh + 1) * w + 2 * bw + 1;
    }
    __syncthreads();

    float vals[16];
    float s = 0.f, s2 = 0.f;
    #pragma unroll
    for (int i = 0; i < 16; i++) {
        int f      = tid + i * 256;
        int c      = f >> 10;
        int within = f & 1023;
        float v = vf[(size_t)srows[c] * HDIM + within];
        vals[i] = v;
        s  += v;
        s2 += v * v;
    }

    #pragma unroll
    for (int o = 16; o > 0; o >>= 1) {
        s  += __shfl_down_sync(0xFFFFFFFFu, s, o);
        s2 += __shfl_down_sync(0xFFFFFFFFu, s2, o);
    }
    if ((tid & 31) == 0) { sred[0][tid >> 5] = s; sred[1][tid >> 5] = s2; }
    __syncthreads();
    if (tid < 32) {
        float a = (tid < 8) ? sred[0][tid] : 0.f;
        float b = (tid < 8) ? sred[1][tid] : 0.f;
        #pragma unroll
        for (int o = 4; o > 0; o >>= 1) {
            a += __shfl_down_sync(0xFFFFFFFFu, a, o);
            b += __shfl_down_sync(0xFFFFFFFFu, b, o);
        }
        if (tid == 0) {
            float mu  = a * (1.0f / IC);
            float var = b * (1.0f / IC) - mu * mu;
            sstat[0] = mu;
            sstat[1] = rsqrtf(var + 1e-5f);
        }
    }
    __syncthreads();

    float mu   = sstat[0];
    float rstd = sstat[1];
    size_t rowb = (size_t)r * IC;
    #pragma unroll
    for (int i = 0; i < 16; i++) {
        int f = tid + i * 256;
        float y = (vals[i] - mu) * rstd * gamma[f] + beta[f];
        g_X[rowb + f] = __float2half_rn(y);
    }
}

// ----------------------------------------------------------------------------
// weight transpose + fp16 convert:  W[K,N] fp32 -> T [N,K] fp16
// ----------------------------------------------------------------------------
__global__ void __launch_bounds__(256) wconv_kernel(
    const float* __restrict__ W,
    __half* __restrict__ T,
    int K, int N)
{
    __shared__ float tile[32][33];
    int tx = threadIdx.x, ty = threadIdx.y;         // 32 x 8
    int n0 = blockIdx.x * 32, k0 = blockIdx.y * 32;
    #pragma unroll
    for (int j = 0; j < 4; j++)
        tile[ty + 8 * j][tx] = W[(size_t)(k0 + ty + 8 * j) * N + n0 + tx];
    __syncthreads();
    #pragma unroll
    for (int j = 0; j < 4; j++) {
        float v = tile[tx][ty + 8 * j];
        T[(size_t)(n0 + ty + 8 * j) * K + k0 + tx] = __float2half_rn(v);
    }
}

// ----------------------------------------------------------------------------
// tcgen05 SS-mode fp16 GEMM, 256x256 CTA tile, KCHUNK=64, SW128:
//   C[M,N] = epi( A[M,K] @ B[N,K]^T + bias ),  single fp16 operands.
//   Stage (64KB): A0 (16KB, 128 rows x 128B) | A1 (16KB) | B (32KB, 256 rows).
//   2 stages.  TMEM: D0 @0..255, D1 @256..511 (alloc 512).
//   Per chunk: 4 k-steps x 2 D tiles = 8 MMAs (N=256, validated in R12).
// ----------------------------------------------------------------------------
#define KCHUNK  64
#define STAGEB  65536
#define DSMEMB  (2 * STAGEB + 1024)
#define IDESC_V ((1u<<4)|(32u<<17)|(8u<<24))   // fp16 in, f32 acc, N=256, M=128

__global__ void __launch_bounds__(256) __cluster_dims__(1, 1, 1) gemm_kernel(
    const __half* __restrict__ A,
    const __half* __restrict__ B,
    const float* __restrict__ bias,
    float* __restrict__ outF,
    __half* __restrict__ outH,
    int M, int K, int Nfull, int mode)
{
#if HAS_TCGEN05
    extern __shared__ char dsm_raw[];
    __shared__ __align__(8) uint64_t s_bar[1];
    __shared__ __align__(4) uint32_t s_tmem[1];

    const int tid = threadIdx.x;
    const int wid = tid >> 5;
    const int bm  = blockIdx.y * 256;
    const int bn  = blockIdx.x * 256;
    const int nk  = K / KCHUNK;

    uint32_t stage = (smem_u32(dsm_raw) + 1023u) & ~1023u;
    uint32_t bMma  = smem_u32(&s_bar[0]);

    if (wid == 0) tmem_alloc(smem_u32(s_tmem), 512);
    if (tid == 0) mbar_init(bMma, 1);
    __syncthreads();
    uint32_t tmem;
    asm volatile("ld.shared.b32 %0, [%1];" : "=r"(tmem) : "r"(smem_u32(s_tmem)));

    const size_t kb = (size_t)K * 2;   // row bytes (fp16)

    // loads one K-chunk into stage buffer (c & 1): 4096 x 16B via cp.async
    auto load_stage = [&](int c) {
        uint32_t sb = stage + (uint32_t)(c & 1) * STAGEB;
        size_t koff = (size_t)c * (KCHUNK * 2);   // 128 bytes per chunk
        #pragma unroll
        for (int i = 0; i < 16; ++i) {
            int q = tid + 256 * i;
            const char* src;
            uint32_t dst;
            if (q < 2048) {                 // A: 2 subtiles x 128 rows x 8 ch
                int plane = q >> 10;
                int idx   = q & 1023;
                int row   = idx >> 3;
                int ch    = idx & 7;
                int grow  = bm + plane * 128 + row;
                src = (const char*)A + (size_t)grow * kb + koff + ch * 16;
                dst = sb + plane * 16384 + SWZ(row * 128 + ch * 16);
            } else {                        // B: 256 rows x 8 ch
                int idx   = q - 2048;
                int row   = idx >> 3;
                int ch    = idx & 7;
                int grow  = bn + row;
                src = (const char*)B + (size_t)grow * kb + koff + ch * 16;
                dst = sb + 32768 + SWZ(row * 128 + ch * 16);
            }
            cp_async16(dst, src);
        }
        cp_commit();
    };

    load_stage(0);

    for (int c = 0; c < nk; ++c) {
        cp_wait0();                 // chunk c resident
        fence_proxy_async_cta();
        tc_fence_before();
        __syncthreads();

        // prefetch next chunk; its buffer was read by MMA (c-1) -> wait it
        if (c + 1 < nk) {
            if (c >= 1) mbar_wait(bMma, (uint32_t)((c - 1) & 1));
            load_stage(c + 1);
        }

        // MMA: warp 0 elect issues 8 MMAs for this chunk (2 D tiles, N=256)
        if (wid == 0) {
            tc_fence_after();
            if (elect_one_pred()) {
                uint32_t sb = stage + (uint32_t)(c & 1) * STAGEB;
                uint64_t dA0 = make_desc(sb);
                uint64_t dA1 = make_desc(sb + 16384);
                uint64_t dB  = make_desc(sb + 32768);
                #pragma unroll
                for (int ks = 0; ks < 4; ++ks) {
                    uint64_t o = (uint64_t)(ks * 2);
                    uint32_t acc = (c > 0 || ks > 0) ? 1u : 0u;
                    mma_f16_ss(tmem,       dA0 + o, dB + o, IDESC_V, acc);
                    mma_f16_ss(tmem + 256, dA1 + o, dB + o, IDESC_V, acc);
                }
                mma_commit(bMma);
            }
        }
    }

    mbar_wait(bMma, (uint32_t)((nk - 1) & 1));
    __syncthreads();
    tc_fence_after();

    // --------- epilogue: 8 warps = 4 row-subparts x 2 M-subtiles -----------
    const int lane = tid & 31;
    const int sub  = wid & 3;          // TMEM lane subpartition
    const int tI   = wid >> 2;         // M subtile / D tile
    const int row  = bm + tI * 128 + sub * 32 + lane;
    const uint32_t woff = ((uint32_t)sub) << 21;

    #pragma unroll 1
    for (int b = 0; b < 8; ++b) {
        uint32_t r[32];
        TCGEN05_LD_X32(r, tmem + tI * 256 + b * 32 + woff);
        tmem_wait_ld();
        int col0 = bn + b * 32;
        if (mode) {
            __align__(16) __half hv[32];
            #pragma unroll
            for (int j = 0; j < 32; ++j) {
                float v = __uint_as_float(r[j]) + bias[col0 + j];
                hv[j] = __float2half_rn(gelu_exact(v));
            }
            uint4* dh = (uint4*)(outH + (size_t)row * Nfull + col0);
            #pragma unroll
            for (int u = 0; u < 4; ++u) dh[u] = ((uint4*)hv)[u];
        } else {
            float* dp = outF + (size_t)row * Nfull + col0;
            #pragma unroll
            for (int j = 0; j < 32; j += 4) {
                float4 v;
                v.x = __uint_as_float(r[j + 0]) + bias[col0 + j + 0];
                v.y = __uint_as_float(r[j + 1]) + bias[col0 + j + 1];
                v.z = __uint_as_float(r[j + 2]) + bias[col0 + j + 2];
                v.w = __uint_as_float(r[j + 3]) + bias[col0 + j + 3];
                *(float4*)(dp + j) = v;
            }
        }
    }

    tc_fence_before();
    __syncthreads();
    if (tid == 0) mbar_inval(bMma);
    __syncthreads();
    if (wid == 0) tmem_dealloc(tmem, 512);

#else  // ------------------- FFMA fallback (plain sm_103 pass) ---------------
    extern __shared__ char dsm_raw[];
    float* As = (float*)dsm_raw;                  // [16][128]
    float* Bs = (float*)(dsm_raw + 16 * 128 * 4); // [16][64]

    const int tid = threadIdx.x & 127;
    const int ty  = tid >> 4;
    const int tx  = tid & 15;
    const int bn0 = blockIdx.x * 256;
    if (threadIdx.x >= 128) return;

    for (int msub = 0; msub < 2; ++msub) {
        const int bm = blockIdx.y * 256 + msub * 128;
        for (int ns = 0; ns < 4; ++ns) {
            int bn = bn0 + ns * 64;
            float acc[16][4];
            #pragma unroll
            for (int i = 0; i < 16; i++)
                #pragma unroll
                for (int j = 0; j < 4; j++) acc[i][j] = 0.f;

            for (int k0 = 0; k0 < K; k0 += 16) {
                #pragma unroll
                for (int i = 0; i < 16; i++) {
                    int idx = tid + 128 * i;
                    int row = idx >> 4, kk = idx & 15;
                    As[kk * 128 + row] = __half2float(A[(size_t)(bm + row) * K + k0 + kk]);
                }
                #pragma unroll
                for (int i = 0; i < 8; i++) {
                    int idx = tid + 128 * i;
                    int n = idx >> 4, kk = idx & 15;
                    Bs[kk * 64 + n] = __half2float(B[(size_t)(bn + n) * K + k0 + kk]);
                }
                __syncthreads();
                #pragma unroll
                for (int kk = 0; kk < 16; kk++) {
                    float bvals[4];
                    #pragma unroll
                    for (int j = 0; j < 4; j++) bvals[j] = Bs[kk * 64 + tx * 4 + j];
                    #pragma unroll
                    for (int i = 0; i < 16; i++) {
                        float av = As[kk * 128 + ty * 16 + i];
                        #pragma unroll
                        for (int j = 0; j < 4; j++) acc[i][j] += av * bvals[j];
                    }
                }
                __syncthreads();
            }

            #pragma unroll
            for (int i = 0; i < 16; i++) {
                int row = bm + ty * 16 + i;
                #pragma unroll
                for (int j = 0; j < 4; j++) {
                    int col = bn + tx * 4 + j;
                    float v = acc[i][j] + bias[col];
                    if (mode) outH[(size_t)row * Nfull + col] = __float2half_rn(gelu_exact(v));
                    else      outF[(size_t)row * Nfull + col] = v;
                }
            }
            __syncthreads();
        }
    }
#endif
}

// ----------------------------------------------------------------------------
extern "C" void kernel_launch(void* const* d_in, const int* in_sizes, int n_in,
                              void* d_out, int out_size)
{
    const float* vf    = (const float*)d_in[0];
    const int*   ss    = (const int*)  d_in[1];
    const float* gamma = (const float*)d_in[2];
    const float* beta  = (const float*)d_in[3];
    const float* w1    = (const float*)d_in[4];
    const float* b1    = (const float*)d_in[5];
    const float* w2    = (const float*)d_in[6];
    const float* b2    = (const float*)d_in[7];
    float* out = (float*)d_out;

    int total_tokens = in_sizes[0] / HDIM;
    int M = total_tokens / 4;
    if (M > MAXM) M = MAXM;

    __half *dX, *dH, *dW1, *dW2;
    cudaGetSymbolAddress((void**)&dX,  g_X);
    cudaGetSymbolAddress((void**)&dH,  g_H);
    cudaGetSymbolAddress((void**)&dW1, g_W1);
    cudaGetSymbolAddress((void**)&dW2, g_W2);

    cudaFuncSetAttribute(gemm_kernel, cudaFuncAttributeMaxDynamicSharedMemorySize, DSMEMB);

    meta_kernel<<<1, 32>>>(ss);
    gather_ln_kernel<<<M, 256>>>(vf, gamma, beta);

    dim3 wb(32, 8);
    wconv_kernel<<<dim3(PH / 32, IC / 32), wb>>>(w1, dW1, IC, PH);
    wconv_kernel<<<dim3(TH / 32, PH / 32), wb>>>(w2, dW2, PH, TH);

    int Mt = (M + 255) / 256;
    gemm_kernel<<<dim3(PH / 256, Mt), 256, DSMEMB>>>(
        dX, dW1, b1, nullptr, dH, M, IC, PH, 1);
    gemm_kernel<<<dim3(TH / 256, Mt), 256, DSMEMB>>>(
        dH, dW2, b2, out, nullptr, M, PH, TH, 0);
}

// round 15
// speedup vs baseline: 2.5120x; 1.1547x over previous
#include <cuda_runtime.h>
#include <cuda_fp16.h>
#include <math.h>
#include <stdint.h>

#define HDIM 1024
#define IC   4096
#define PH   4096
#define TH   2048
#define NTILES 30
#define MAXM 14592

#if defined(__CUDA_ARCH__)
#  if defined(__CUDA_ARCH_FEAT_SM103_ALL) || defined(__CUDA_ARCH_FEAT_SM100_ALL) || \
      defined(__CUDA_ARCH_FEAT_SM101_ALL) || \
      (defined(__CUDA_ARCH_SPECIFIC__) && (__CUDA_ARCH_SPECIFIC__ >= 1000))
#    define HAS_TCGEN05 1
#  else
#    define HAS_TCGEN05 0
#  endif
#else
#  define HAS_TCGEN05 0
#endif

// ------------------------- device scratch (no allocs) -----------------------
__device__ int    g_meta[NTILES * 4];
__device__ __half g_X [(size_t)MAXM * IC];     // post-LN fp16
__device__ __half g_H [(size_t)MAXM * PH];     // post-GELU fp16
__device__ __half g_W1[(size_t)PH * IC];       // W1^T fp16 [N,K]
__device__ __half g_W2[(size_t)TH * PH];       // W2^T fp16 [N,K]

// ------------------------------ helpers ------------------------------------
__device__ __forceinline__ float gelu_exact(float x) {
    return 0.5f * x * (1.0f + erff(x * 0.70710678118654752440f));
}

#if HAS_TCGEN05
__device__ __forceinline__ uint32_t smem_u32(const void* p) {
    uint32_t a;
    asm("{ .reg .u64 t; cvta.to.shared.u64 t, %1; cvt.u32.u64 %0, t; }" : "=r"(a) : "l"(p));
    return a;
}

__device__ __forceinline__ uint32_t elect_one_pred() {
    uint32_t pred;
    asm volatile(
        "{\n\t.reg .pred p;\n\t"
        "elect.sync _|p, 0xFFFFFFFF;\n\t"
        "selp.b32 %0, 1, 0, p;\n\t}"
        : "=r"(pred));
    return pred;
}

__device__ __forceinline__ void mbar_init(uint32_t m, uint32_t cnt) {
    asm volatile("mbarrier.init.shared.b64 [%0], %1;" :: "r"(m), "r"(cnt) : "memory");
}
__device__ __forceinline__ void mbar_inval(uint32_t m) {
    asm volatile("mbarrier.inval.shared.b64 [%0];" :: "r"(m) : "memory");
}
__device__ __forceinline__ void mbar_wait(uint32_t m, uint32_t phase) {
    asm volatile(
        "{\n\t.reg .pred P;\n\t"
        "LAB_WAIT_%=:\n\t"
        "mbarrier.try_wait.parity.acquire.cta.shared::cta.b64 P, [%0], %1, 0x989680;\n\t"
        "@P bra LAB_DONE_%=;\n\t"
        "bra LAB_WAIT_%=;\n\t"
        "LAB_DONE_%=:\n\t}"
        :: "r"(m), "r"(phase) : "memory");
}

__device__ __forceinline__ void cp_async16(uint32_t dst, const void* src) {
    asm volatile("cp.async.cg.shared.global [%0], [%1], 16;" :: "r"(dst), "l"(src) : "memory");
}
__device__ __forceinline__ void cp_commit() {
    asm volatile("cp.async.commit_group;" ::: "memory");
}
__device__ __forceinline__ void cp_wait0() {
    asm volatile("cp.async.wait_group 0;" ::: "memory");
}
__device__ __forceinline__ void cp_wait1() {
    asm volatile("cp.async.wait_group 1;" ::: "memory");
}
__device__ __forceinline__ void fence_proxy_async_cta() {
    asm volatile("fence.proxy.async.shared::cta;" ::: "memory");
}

__device__ __forceinline__ void tmem_alloc(uint32_t smem_dst, uint32_t ncols) {
    asm volatile("tcgen05.alloc.cta_group::1.sync.aligned.shared::cta.b32 [%0], %1;"
                 :: "r"(smem_dst), "r"(ncols) : "memory");
}
__device__ __forceinline__ void tmem_dealloc(uint32_t tmem, uint32_t ncols) {
    asm volatile("tcgen05.dealloc.cta_group::1.sync.aligned.b32 %0, %1;" :: "r"(tmem), "r"(ncols));
}

// SS f16 MMA, cg1, 4-reg disable-lane vector
__device__ __forceinline__ void mma_f16_ss(uint32_t d, uint64_t ad, uint64_t bd,
                                           uint32_t idesc, uint32_t en) {
    asm volatile(
        "{\n\t.reg .pred p;\n\t"
        "setp.ne.u32 p, %4, 0;\n\t"
        "tcgen05.mma.cta_group::1.kind::f16 [%0], %1, %2, %3, {%5, %5, %5, %5}, p;\n\t}"
        :: "r"(d), "l"(ad), "l"(bd), "r"(idesc), "r"(en), "r"(0u) : "memory");
}

__device__ __forceinline__ void mma_commit(uint32_t mbar) {
    asm volatile(
        "tcgen05.commit.cta_group::1.mbarrier::arrive::one.shared::cluster.b64 [%0];"
        :: "r"(mbar) : "memory");
}

#define TCGEN05_LD_X32(r, addr) \
    asm volatile( \
        "tcgen05.ld.sync.aligned.32x32b.x32.b32 " \
        "{%0, %1, %2, %3, %4, %5, %6, %7, " \
        " %8, %9, %10, %11, %12, %13, %14, %15, " \
        " %16, %17, %18, %19, %20, %21, %22, %23, " \
        " %24, %25, %26, %27, %28, %29, %30, %31}, [%32];" \
        : "=r"((r)[0]),  "=r"((r)[1]),  "=r"((r)[2]),  "=r"((r)[3]), \
          "=r"((r)[4]),  "=r"((r)[5]),  "=r"((r)[6]),  "=r"((r)[7]), \
          "=r"((r)[8]),  "=r"((r)[9]),  "=r"((r)[10]), "=r"((r)[11]), \
          "=r"((r)[12]), "=r"((r)[13]), "=r"((r)[14]), "=r"((r)[15]), \
          "=r"((r)[16]), "=r"((r)[17]), "=r"((r)[18]), "=r"((r)[19]), \
          "=r"((r)[20]), "=r"((r)[21]), "=r"((r)[22]), "=r"((r)[23]), \
          "=r"((r)[24]), "=r"((r)[25]), "=r"((r)[26]), "=r"((r)[27]), \
          "=r"((r)[28]), "=r"((r)[29]), "=r"((r)[30]), "=r"((r)[31]) \
        : "r"(addr))

__device__ __forceinline__ void tmem_wait_ld() {
    asm volatile("tcgen05.wait::ld.sync.aligned;" ::: "memory");
}
__device__ __forceinline__ void tc_fence_after() {
    asm volatile("tcgen05.fence::after_thread_sync;" ::: "memory");
}
__device__ __forceinline__ void tc_fence_before() {
    asm volatile("tcgen05.fence::before_thread_sync;" ::: "memory");
}

// SW128 K-major descriptor (verified): layout=2, version=1, SBO=64, LBO=1
static __device__ __forceinline__ uint64_t make_desc(uint32_t addr) {
    const uint64_t base = (2ull << 61) | (1ull << 46) | (64ull << 32) | (1ull << 16);
    return base | ((uint64_t)(addr >> 4) & 0x3FFF);
}
#endif  // HAS_TCGEN05

#define SWZ(x) ((x) ^ (((x) >> 3) & 0x70))

// ----------------------------------------------------------------------------
__global__ void meta_kernel(const int* __restrict__ ss) {
    if (threadIdx.x == 0 && blockIdx.x == 0) {
        int is64 = (ss[1] == 0) ? 1 : 0;
        int in_off = 0, out_off = 0;
        for (int t = 0; t < NTILES; t++) {
            int h, w;
            if (is64) { h = ss[4 * t]; w = ss[4 * t + 2]; }
            else      { h = ss[2 * t]; w = ss[2 * t + 1]; }
            g_meta[4 * t + 0] = h;
            g_meta[4 * t + 1] = w;
            g_meta[4 * t + 2] = in_off;
            g_meta[4 * t + 3] = out_off;
            in_off  += h * w;
            out_off += (h >> 1) * (w >> 1);
        }
    }
}

// ----------------------------------------------------------------------------
// gather + LayerNorm -> fp16
// ----------------------------------------------------------------------------
__global__ void __launch_bounds__(256) gather_ln_kernel(
    const float* __restrict__ vf,
    const float* __restrict__ gamma,
    const float* __restrict__ beta)
{
    const int r   = blockIdx.x;
    const int tid = threadIdx.x;

    __shared__ int   srows[4];
    __shared__ float sred[2][8];
    __shared__ float sstat[2];

    if (tid == 0) {
        int t = 0;
        #pragma unroll 1
        for (int i = 0; i < NTILES; i++) {
            int h  = g_meta[4 * i + 0];
            int w  = g_meta[4 * i + 1];
            int oo = g_meta[4 * i + 3];
            int cnt = (h >> 1) * (w >> 1);
            if (r >= oo && r < oo + cnt) { t = i; break; }
        }
        int w  = g_meta[4 * t + 1];
        int io = g_meta[4 * t + 2];
        int oo = g_meta[4 * t + 3];
        int local = r - oo;
        int wb = w >> 1;
        int bh = local / wb;
        int bw = local - bh * wb;
        srows[0] = io + (2 * bh)     * w + 2 * bw;
        srows[1] = io + (2 * bh)     * w + 2 * bw + 1;
        srows[2] = io + (2 * bh + 1) * w + 2 * bw;
        srows[3] = io + (2 * bh + 1) * w + 2 * bw + 1;
    }
    __syncthreads();

    float vals[16];
    float s = 0.f, s2 = 0.f;
    #pragma unroll
    for (int i = 0; i < 16; i++) {
        int f      = tid + i * 256;
        int c      = f >> 10;
        int within = f & 1023;
        float v = vf[(size_t)srows[c] * HDIM + within];
        vals[i] = v;
        s  += v;
        s2 += v * v;
    }

    #pragma unroll
    for (int o = 16; o > 0; o >>= 1) {
        s  += __shfl_down_sync(0xFFFFFFFFu, s, o);
        s2 += __shfl_down_sync(0xFFFFFFFFu, s2, o);
    }
    if ((tid & 31) == 0) { sred[0][tid >> 5] = s; sred[1][tid >> 5] = s2; }
    __syncthreads();
    if (tid < 32) {
        float a = (tid < 8) ? sred[0][tid] : 0.f;
        float b = (tid < 8) ? sred[1][tid] : 0.f;
        #pragma unroll
        for (int o = 4; o > 0; o >>= 1) {
            a += __shfl_down_sync(0xFFFFFFFFu, a, o);
            b += __shfl_down_sync(0xFFFFFFFFu, b, o);
        }
        if (tid == 0) {
            float mu  = a * (1.0f / IC);
            float var = b * (1.0f / IC) - mu * mu;
            sstat[0] = mu;
            sstat[1] = rsqrtf(var + 1e-5f);
        }
    }
    __syncthreads();

    float mu   = sstat[0];
    float rstd = sstat[1];
    size_t rowb = (size_t)r * IC;
    #pragma unroll
    for (int i = 0; i < 16; i++) {
        int f = tid + i * 256;
        float y = (vals[i] - mu) * rstd * gamma[f] + beta[f];
        g_X[rowb + f] = __float2half_rn(y);
    }
}

// ----------------------------------------------------------------------------
// weight transpose + fp16 convert:  W[K,N] fp32 -> T [N,K] fp16
// ----------------------------------------------------------------------------
__global__ void __launch_bounds__(256) wconv_kernel(
    const float* __restrict__ W,
    __half* __restrict__ T,
    int K, int N)
{
    __shared__ float tile[32][33];
    int tx = threadIdx.x, ty = threadIdx.y;         // 32 x 8
    int n0 = blockIdx.x * 32, k0 = blockIdx.y * 32;
    #pragma unroll
    for (int j = 0; j < 4; j++)
        tile[ty + 8 * j][tx] = W[(size_t)(k0 + ty + 8 * j) * N + n0 + tx];
    __syncthreads();
    #pragma unroll
    for (int j = 0; j < 4; j++) {
        float v = tile[tx][ty + 8 * j];
        T[(size_t)(n0 + ty + 8 * j) * K + k0 + tx] = __float2half_rn(v);
    }
}

// ----------------------------------------------------------------------------
// tcgen05 SS-mode fp16 GEMM, 256x256 CTA tile, KCHUNK=64, SW128, 3 stages:
//   C[M,N] = epi( A[M,K] @ B[N,K]^T + bias ),  single fp16 operands.
//   Stage (64KB): A0 (16KB) | A1 (16KB) | B (32KB).  3 stages (192KB).
//   Two cp.async groups in flight per CTA (wait_group 1), in-order completion.
//   TMEM: D0 @0..255, D1 @256..511 (alloc 512).  8 MMAs/chunk.
// ----------------------------------------------------------------------------
#define KCHUNK  64
#define STAGEB  65536
#define NSTG    3
#define DSMEMB  (NSTG * STAGEB + 1024)
#define IDESC_V ((1u<<4)|(32u<<17)|(8u<<24))   // fp16 in, f32 acc, N=256, M=128

__global__ void __launch_bounds__(256) __cluster_dims__(1, 1, 1) gemm_kernel(
    const __half* __restrict__ A,
    const __half* __restrict__ B,
    const float* __restrict__ bias,
    float* __restrict__ outF,
    __half* __restrict__ outH,
    int M, int K, int Nfull, int mode)
{
#if HAS_TCGEN05
    extern __shared__ char dsm_raw[];
    __shared__ __align__(8) uint64_t s_bar[1];
    __shared__ __align__(4) uint32_t s_tmem[1];

    const int tid = threadIdx.x;
    const int wid = tid >> 5;
    const int bm  = blockIdx.y * 256;
    const int bn  = blockIdx.x * 256;
    const int nk  = K / KCHUNK;

    uint32_t stage = (smem_u32(dsm_raw) + 1023u) & ~1023u;
    uint32_t bMma  = smem_u32(&s_bar[0]);

    if (wid == 0) tmem_alloc(smem_u32(s_tmem), 512);
    if (tid == 0) mbar_init(bMma, 1);
    __syncthreads();
    uint32_t tmem;
    asm volatile("ld.shared.b32 %0, [%1];" : "=r"(tmem) : "r"(smem_u32(s_tmem)));

    const size_t kb = (size_t)K * 2;   // row bytes (fp16)

    // stage index: c % 3
    auto load_stage = [&](int c) {
        int s = c % NSTG;
        uint32_t sb = stage + (uint32_t)s * STAGEB;
        size_t koff = (size_t)c * (KCHUNK * 2);   // 128 bytes per chunk
        #pragma unroll
        for (int i = 0; i < 16; ++i) {
            int q = tid + 256 * i;
            const char* src;
            uint32_t dst;
            if (q < 2048) {                 // A: 2 subtiles x 128 rows x 8 ch
                int plane = q >> 10;
                int idx   = q & 1023;
                int row   = idx >> 3;
                int ch    = idx & 7;
                int grow  = bm + plane * 128 + row;
                src = (const char*)A + (size_t)grow * kb + koff + ch * 16;
                dst = sb + plane * 16384 + SWZ(row * 128 + ch * 16);
            } else {                        // B: 256 rows x 8 ch
                int idx   = q - 2048;
                int row   = idx >> 3;
                int ch    = idx & 7;
                int grow  = bn + row;
                src = (const char*)B + (size_t)grow * kb + koff + ch * 16;
                dst = sb + 32768 + SWZ(row * 128 + ch * 16);
            }
            cp_async16(dst, src);
        }
        cp_commit();
    };

    // prologue: two chunks in flight
    load_stage(0);
    if (nk > 1) load_stage(1);

    for (int c = 0; c < nk; ++c) {
        // chunk c resident: groups complete in-order, so "<=1 pending" means
        // the pending one (if any) is chunk c+1.
        if (c + 1 < nk) cp_wait1();
        else            cp_wait0();
        fence_proxy_async_cta();
        tc_fence_before();
        __syncthreads();

        // issue load for chunk c+2 into buffer (c+2)%3; that buffer was used
        // by chunk c-1, whose MMA must be complete first.
        if (c + 2 < nk) {
            if (c >= 1) mbar_wait(bMma, (uint32_t)((c - 1) & 1));
            load_stage(c + 2);
        }

        // MMA: warp 0 elect issues 8 MMAs for this chunk (2 D tiles, N=256)
        if (wid == 0) {
            tc_fence_after();
            if (elect_one_pred()) {
                uint32_t sb = stage + (uint32_t)(c % NSTG) * STAGEB;
                uint64_t dA0 = make_desc(sb);
                uint64_t dA1 = make_desc(sb + 16384);
                uint64_t dB  = make_desc(sb + 32768);
                #pragma unroll
                for (int ks = 0; ks < 4; ++ks) {
                    uint64_t o = (uint64_t)(ks * 2);
                    uint32_t acc = (c > 0 || ks > 0) ? 1u : 0u;
                    mma_f16_ss(tmem,       dA0 + o, dB + o, IDESC_V, acc);
                    mma_f16_ss(tmem + 256, dA1 + o, dB + o, IDESC_V, acc);
                }
                mma_commit(bMma);
            }
        }
    }

    mbar_wait(bMma, (uint32_t)((nk - 1) & 1));
    __syncthreads();
    tc_fence_after();

    // --------- epilogue: 8 warps = 4 row-subparts x 2 M-subtiles -----------
    const int lane = tid & 31;
    const int sub  = wid & 3;          // TMEM lane subpartition
    const int tI   = wid >> 2;         // M subtile / D tile
    const int row  = bm + tI * 128 + sub * 32 + lane;
    const uint32_t woff = ((uint32_t)sub) << 21;

    #pragma unroll 1
    for (int b = 0; b < 8; ++b) {
        uint32_t r[32];
        TCGEN05_LD_X32(r, tmem + tI * 256 + b * 32 + woff);
        tmem_wait_ld();
        int col0 = bn + b * 32;
        if (mode) {
            __align__(16) __half hv[32];
            #pragma unroll
            for (int j = 0; j < 32; ++j) {
                float v = __uint_as_float(r[j]) + bias[col0 + j];
                hv[j] = __float2half_rn(gelu_exact(v));
            }
            uint4* dh = (uint4*)(outH + (size_t)row * Nfull + col0);
            #pragma unroll
            for (int u = 0; u < 4; ++u) dh[u] = ((uint4*)hv)[u];
        } else {
            float* dp = outF + (size_t)row * Nfull + col0;
            #pragma unroll
            for (int j = 0; j < 32; j += 4) {
                float4 v;
                v.x = __uint_as_float(r[j + 0]) + bias[col0 + j + 0];
                v.y = __uint_as_float(r[j + 1]) + bias[col0 + j + 1];
                v.z = __uint_as_float(r[j + 2]) + bias[col0 + j + 2];
                v.w = __uint_as_float(r[j + 3]) + bias[col0 + j + 3];
                *(float4*)(dp + j) = v;
            }
        }
    }

    tc_fence_before();
    __syncthreads();
    if (tid == 0) mbar_inval(bMma);
    __syncthreads();
    if (wid == 0) tmem_dealloc(tmem, 512);

#else  // ------------------- FFMA fallback (plain sm_103 pass) ---------------
    extern __shared__ char dsm_raw[];
    float* As = (float*)dsm_raw;                  // [16][128]
    float* Bs = (float*)(dsm_raw + 16 * 128 * 4); // [16][64]

    const int tid = threadIdx.x & 127;
    const int ty  = tid >> 4;
    const int tx  = tid & 15;
    const int bn0 = blockIdx.x * 256;
    if (threadIdx.x >= 128) return;

    for (int msub = 0; msub < 2; ++msub) {
        const int bm = blockIdx.y * 256 + msub * 128;
        for (int ns = 0; ns < 4; ++ns) {
            int bn = bn0 + ns * 64;
            float acc[16][4];
            #pragma unroll
            for (int i = 0; i < 16; i++)
                #pragma unroll
                for (int j = 0; j < 4; j++) acc[i][j] = 0.f;

            for (int k0 = 0; k0 < K; k0 += 16) {
                #pragma unroll
                for (int i = 0; i < 16; i++) {
                    int idx = tid + 128 * i;
                    int row = idx >> 4, kk = idx & 15;
                    As[kk * 128 + row] = __half2float(A[(size_t)(bm + row) * K + k0 + kk]);
                }
                #pragma unroll
                for (int i = 0; i < 8; i++) {
                    int idx = tid + 128 * i;
                    int n = idx >> 4, kk = idx & 15;
                    Bs[kk * 64 + n] = __half2float(B[(size_t)(bn + n) * K + k0 + kk]);
                }
                __syncthreads();
                #pragma unroll
                for (int kk = 0; kk < 16; kk++) {
                    float bvals[4];
                    #pragma unroll
                    for (int j = 0; j < 4; j++) bvals[j] = Bs[kk * 64 + tx * 4 + j];
                    #pragma unroll
                    for (int i = 0; i < 16; i++) {
                        float av = As[kk * 128 + ty * 16 + i];
                        #pragma unroll
                        for (int j = 0; j < 4; j++) acc[i][j] += av * bvals[j];
                    }
                }
                __syncthreads();
            }

            #pragma unroll
            for (int i = 0; i < 16; i++) {
                int row = bm + ty * 16 + i;
                #pragma unroll
                for (int j = 0; j < 4; j++) {
                    int col = bn + tx * 4 + j;
                    float v = acc[i][j] + bias[col];
                    if (mode) outH[(size_t)row * Nfull + col] = __float2half_rn(gelu_exact(v));
                    else      outF[(size_t)row * Nfull + col] = v;
                }
            }
            __syncthreads();
        }
    }
#endif
}

// ----------------------------------------------------------------------------
extern "C" void kernel_launch(void* const* d_in, const int* in_sizes, int n_in,
                              void* d_out, int out_size)
{
    const float* vf    = (const float*)d_in[0];
    const int*   ss    = (const int*)  d_in[1];
    const float* gamma = (const float*)d_in[2];
    const float* beta  = (const float*)d_in[3];
    const float* w1    = (const float*)d_in[4];
    const float* b1    = (const float*)d_in[5];
    const float* w2    = (const float*)d_in[6];
    const float* b2    = (const float*)d_in[7];
    float* out = (float*)d_out;

    int total_tokens = in_sizes[0] / HDIM;
    int M = total_tokens / 4;
    if (M > MAXM) M = MAXM;

    __half *dX, *dH, *dW1, *dW2;
    cudaGetSymbolAddress((void**)&dX,  g_X);
    cudaGetSymbolAddress((void**)&dH,  g_H);
    cudaGetSymbolAddress((void**)&dW1, g_W1);
    cudaGetSymbolAddress((void**)&dW2, g_W2);

    cudaFuncSetAttribute(gemm_kernel, cudaFuncAttributeMaxDynamicSharedMemorySize, DSMEMB);

    meta_kernel<<<1, 32>>>(ss);
    gather_ln_kernel<<<M, 256>>>(vf, gamma, beta);

    dim3 wb(32, 8);
    wconv_kernel<<<dim3(PH / 32, IC / 32), wb>>>(w1, dW1, IC, PH);
    wconv_kernel<<<dim3(TH / 32, PH / 32), wb>>>(w2, dW2, PH, TH);

    int Mt = (M + 255) / 256;
    gemm_kernel<<<dim3(PH / 256, Mt), 256, DSMEMB>>>(
        dX, dW1, b1, nullptr, dH, M, IC, PH, 1);
    gemm_kernel<<<dim3(TH / 256, Mt), 256, DSMEMB>>>(
        dH, dW2, b2, out, nullptr, M, PH, TH, 0);
}